// round 3
// baseline (speedup 1.0000x reference)
#include <cuda_runtime.h>
#include <math.h>

#define HD   1024
#define ED   1024
#define TD   4096
#define VD   50257
#define INPD 2049
#define JC   8            // j-chunks for vocab matvec
#define JCH  (HD / JC)    // 128 j per chunk
#define K3_VPT 4

// ---- scratch (no allocations allowed) ----
__device__ float g_part[32][ED];     // partial column sums of hiddens
__device__ float g_att[ED];          // att_result = colsum(hiddens)
__device__ float g_h[HD];            // LSTM output h
__device__ float g_lpart[JC][50304]; // partial logits per j-chunk
__device__ float g_logits[50304];    // h @ dim_out
__device__ float g_red[2];           // [0]=max, [1]=1/sum

// ============================================================
// K1a: partial column sums of hiddens [T,E], float4-vectorized.
// grid (ED/4/64, 32), block 64. block y owns TD/32 = 128 rows.
// ============================================================
__global__ void k_colsum_part(const float* __restrict__ hiddens) {
    int c4 = blockIdx.x * 64 + threadIdx.x;          // float4 column index
    int r0 = blockIdx.y * (TD / 32);
    const float4* h4 = (const float4*)hiddens;
    float4 s = make_float4(0.f, 0.f, 0.f, 0.f);
    #pragma unroll 8
    for (int r = 0; r < TD / 32; ++r) {
        float4 v = h4[(size_t)(r0 + r) * (ED / 4) + c4];
        s.x += v.x; s.y += v.y; s.z += v.z; s.w += v.w;
    }
    ((float4*)g_part[blockIdx.y])[c4] = s;
}

// K1b: reduce 32 partials -> g_att
__global__ void k_colsum_final() {
    int c4 = blockIdx.x * 64 + threadIdx.x;
    float4 s = make_float4(0.f, 0.f, 0.f, 0.f);
    #pragma unroll
    for (int p = 0; p < 32; ++p) {
        float4 v = ((const float4*)g_part[p])[c4];
        s.x += v.x; s.y += v.y; s.z += v.z; s.w += v.w;
    }
    ((float4*)g_att)[c4] = s;
}

// ============================================================
// K2: LSTM gates. One block (256 thr) per output row r.
//   gate = act( W_i[r,:] @ x + b_i[r] + W_h[r,:] @ cur_h + b_h[r] )
//   x = [sen_emb (1024), g_att (1024), pos]
// ============================================================
__device__ __forceinline__ float sigm(float x) { return 1.f / (1.f + __expf(-x)); }

__global__ void k_gates(
    const float* __restrict__ sen_emb,
    const float* __restrict__ Wii, const float* __restrict__ Wih,
    const float* __restrict__ bii, const float* __restrict__ bih,
    const float* __restrict__ Wfi, const float* __restrict__ Wfh,
    const float* __restrict__ bfi, const float* __restrict__ bfh,
    const float* __restrict__ Wci, const float* __restrict__ Wch,
    const float* __restrict__ bci, const float* __restrict__ bch,
    const float* __restrict__ Woi, const float* __restrict__ Woh,
    const float* __restrict__ boi, const float* __restrict__ boh,
    const float* __restrict__ cur_h, const float* __restrict__ cur_cell,
    const int*   __restrict__ pos_raw)
{
    const int r   = blockIdx.x;
    const int tid = threadIdx.x;
    const size_t oi = (size_t)r * INPD;
    const size_t oh = (size_t)r * HD;

    float ai = 0.f, af = 0.f, ag = 0.f, ao = 0.f;

    // x[0:1024] = sen_emb
    for (int k = tid; k < ED; k += 256) {
        float xv = sen_emb[k];
        ai += Wii[oi + k] * xv;
        af += Wfi[oi + k] * xv;
        ag += Wci[oi + k] * xv;
        ao += Woi[oi + k] * xv;
    }
    // x[1024:2048] = att_result
    for (int k = tid; k < ED; k += 256) {
        float xv = g_att[k];
        ai += Wii[oi + 1024 + k] * xv;
        af += Wfi[oi + 1024 + k] * xv;
        ag += Wci[oi + 1024 + k] * xv;
        ao += Woi[oi + 1024 + k] * xv;
    }
    // hidden-state part (cur_h is zeros in the dataset, but stay general)
    for (int k = tid; k < HD; k += 256) {
        float hv = cur_h[k];
        ai += Wih[oh + k] * hv;
        af += Wfh[oh + k] * hv;
        ag += Wch[oh + k] * hv;
        ao += Woh[oh + k] * hv;
    }
    // x[2048] = pos_index (robust decode: small int bits vs float bits)
    if (tid == 0) {
        int raw = pos_raw[0];
        float pos = (raw >= -1000000 && raw <= 1000000) ? (float)raw
                                                        : __int_as_float(raw);
        ai += Wii[oi + 2048] * pos;
        af += Wfi[oi + 2048] * pos;
        ag += Wci[oi + 2048] * pos;
        ao += Woi[oi + 2048] * pos;
    }

    // reduce 4 accumulators across the block
    #pragma unroll
    for (int o = 16; o; o >>= 1) {
        ai += __shfl_down_sync(0xffffffffu, ai, o);
        af += __shfl_down_sync(0xffffffffu, af, o);
        ag += __shfl_down_sync(0xffffffffu, ag, o);
        ao += __shfl_down_sync(0xffffffffu, ao, o);
    }
    __shared__ float s4[8][4];
    int wid = tid >> 5, lane = tid & 31;
    if (lane == 0) { s4[wid][0] = ai; s4[wid][1] = af; s4[wid][2] = ag; s4[wid][3] = ao; }
    __syncthreads();
    if (tid == 0) {
        float vi = 0.f, vf = 0.f, vg = 0.f, vo = 0.f;
        #pragma unroll
        for (int w = 0; w < 8; ++w) {
            vi += s4[w][0]; vf += s4[w][1]; vg += s4[w][2]; vo += s4[w][3];
        }
        vi += bii[r] + bih[r];
        vf += bfi[r] + bfh[r];
        vg += bci[r] + bch[r];
        vo += boi[r] + boh[r];
        float i = sigm(vi), f = sigm(vf), g = tanhf(vg), o = sigm(vo);
        float c = f * cur_cell[r] + i * g;
        g_h[r] = o * tanhf(c);
    }
}

// ============================================================
// K3a: partial logits. grid (ceil(VD/1024), JC), block 256.
// Block (bx, jc): v-range [bx*1024, bx*1024+1024), j-range
// [jc*128, jc*128+128). 4 consecutive v per thread -> 4 indep
// accumulator chains, MLP ~32. Fully coalesced over v.
// ============================================================
__global__ void k_vocab_part(const float* __restrict__ dim_out) {
    __shared__ float hs[JCH];
    const int jc = blockIdx.y;
    const int j0 = jc * JCH;
    for (int j = threadIdx.x; j < JCH; j += 256) hs[j] = g_h[j0 + j];
    __syncthreads();

    int v0 = (blockIdx.x * 256 + threadIdx.x) * K3_VPT;
    if (v0 >= VD) return;
    float a0 = 0.f, a1 = 0.f, a2 = 0.f, a3 = 0.f;
    const float* p = dim_out + (size_t)j0 * VD + v0;
    if (v0 + K3_VPT <= VD) {
        #pragma unroll 8
        for (int j = 0; j < JCH; ++j) {
            float hj = hs[j];
            const float* pj = p + (size_t)j * VD;
            a0 += hj * pj[0];
            a1 += hj * pj[1];
            a2 += hj * pj[2];
            a3 += hj * pj[3];
        }
        g_lpart[jc][v0 + 0] = a0;
        g_lpart[jc][v0 + 1] = a1;
        g_lpart[jc][v0 + 2] = a2;
        g_lpart[jc][v0 + 3] = a3;
    } else {
        for (int v = v0; v < VD; ++v) {
            float acc = 0.f;
            #pragma unroll 8
            for (int j = 0; j < JCH; ++j)
                acc += hs[j] * dim_out[(size_t)(j0 + j) * VD + v];
            g_lpart[jc][v] = acc;
        }
    }
}

// K3b: sum JC partials -> g_logits
__global__ void k_vocab_final() {
    int v = blockIdx.x * 256 + threadIdx.x;
    if (v >= VD) return;
    float s = 0.f;
    #pragma unroll
    for (int c = 0; c < JC; ++c) s += g_lpart[c][v];
    g_logits[v] = s;
}

// ============================================================
// K4: single-block max + sum(exp) over logits (L2-resident)
// ============================================================
__global__ void k_reduce() {
    const int tid = threadIdx.x;   // 1024 threads
    __shared__ float sw[32];
    float m = -INFINITY;
    for (int v = tid; v < VD; v += 1024) m = fmaxf(m, g_logits[v]);
    #pragma unroll
    for (int o = 16; o; o >>= 1) m = fmaxf(m, __shfl_down_sync(0xffffffffu, m, o));
    if ((tid & 31) == 0) sw[tid >> 5] = m;
    __syncthreads();
    if (tid < 32) {
        float t = sw[tid];
        #pragma unroll
        for (int o = 16; o; o >>= 1) t = fmaxf(t, __shfl_down_sync(0xffffffffu, t, o));
        if (tid == 0) sw[0] = t;
    }
    __syncthreads();
    float bm = sw[0];
    __syncthreads();   // protect sw reuse
    float s = 0.f;
    for (int v = tid; v < VD; v += 1024) s += expf(g_logits[v] - bm);
    #pragma unroll
    for (int o = 16; o; o >>= 1) s += __shfl_down_sync(0xffffffffu, s, o);
    if ((tid & 31) == 0) sw[tid >> 5] = s;
    __syncthreads();
    if (tid < 32) {
        float t = sw[tid];
        #pragma unroll
        for (int o = 16; o; o >>= 1) t += __shfl_down_sync(0xffffffffu, t, o);
        if (tid == 0) { g_red[0] = bm; g_red[1] = 1.f / t; }
    }
}

// K5: out[v] = exp(logit - max) * inv_sum
__global__ void k_norm(float* __restrict__ out) {
    int v = blockIdx.x * 256 + threadIdx.x;
    if (v < VD) out[v] = expf(g_logits[v] - g_red[0]) * g_red[1];
}

// ============================================================
extern "C" void kernel_launch(void* const* d_in, const int* in_sizes, int n_in,
                              void* d_out, int out_size)
{
    const float* sen_emb  = (const float*)d_in[0];
    const float* hiddens  = (const float*)d_in[1];
    const float* dim_out  = (const float*)d_in[2];
    const float* Wii = (const float*)d_in[3];
    const float* Wih = (const float*)d_in[4];
    const float* bii = (const float*)d_in[5];
    const float* bih = (const float*)d_in[6];
    const float* Wfi = (const float*)d_in[7];
    const float* Wfh = (const float*)d_in[8];
    const float* bfi = (const float*)d_in[9];
    const float* bfh = (const float*)d_in[10];
    const float* Wci = (const float*)d_in[11];
    const float* Wch = (const float*)d_in[12];
    const float* bci = (const float*)d_in[13];
    const float* bch = (const float*)d_in[14];
    const float* Woi = (const float*)d_in[15];
    const float* Woh = (const float*)d_in[16];
    const float* boi = (const float*)d_in[17];
    const float* boh = (const float*)d_in[18];
    const float* cur_h    = (const float*)d_in[19];
    const float* cur_cell = (const float*)d_in[20];
    const int*   pos_raw  = (const int*)d_in[21];
    float* out = (float*)d_out;

    // K1: att_result = colsum(hiddens)  (softmax over size-1 axis == all ones)
    dim3 g1(ED / 4 / 64, 32);
    k_colsum_part<<<g1, 64>>>(hiddens);
    k_colsum_final<<<ED / 4 / 64, 64>>>();

    // K2: LSTM cell -> g_h
    k_gates<<<HD, 256>>>(sen_emb,
                         Wii, Wih, bii, bih,
                         Wfi, Wfh, bfi, bfh,
                         Wci, Wch, bci, bch,
                         Woi, Woh, boi, boh,
                         cur_h, cur_cell, pos_raw);

    // K3: vocab projection, split over v and j (400 CTAs -> full chip)
    int nbv = (VD + 256 * K3_VPT - 1) / (256 * K3_VPT);   // 50
    dim3 g3(nbv, JC);
    k_vocab_part<<<g3, 256>>>(dim_out);
    int nb = (VD + 255) / 256;                            // 197
    k_vocab_final<<<nb, 256>>>();

    // K4/K5: softmax
    k_reduce<<<1, 1024>>>();
    k_norm<<<nb, 256>>>(out);
}

// round 17
// speedup vs baseline: 1.0004x; 1.0004x over previous
#include <cuda_runtime.h>
#include <math.h>

#define HD   1024
#define ED   1024
#define TD   4096
#define VD   50257
#define INPD 2049
#define JC   32           // j-chunks for vocab matvec
#define JCH  (HD / JC)    // 32 j per chunk
#define K3_VPT 4
#define NBF  50           // stat blocks: 50*256*4 = 51200 >= VD
#define NSPLIT 128        // row splits for colsum (128 CTAs x 256 thr)

// ---- scratch (no allocations allowed) ----
__device__ float g_part[NSPLIT][ED];               // partial column sums of hiddens
__device__ float g_att[ED];                        // att_result = colsum(hiddens)
__device__ float g_h[HD];                          // LSTM output h
__device__ __align__(16) float g_lpart[JC][50304]; // partial logits per j-chunk
__device__ __align__(16) float g_logits[50304];    // h @ dim_out
__device__ float g_bmax[NBF];                      // per-block max of logits
__device__ float g_bsum[NBF];                      // per-block sum exp(l - bmax)

// ============================================================
// K1a: partial column sums of hiddens [T,E], float4-vectorized.
// grid NSPLIT=128, block 256 (covers all 256 float4 columns).
// Each block sums TD/NSPLIT = 32 rows.
// ============================================================
__global__ void k_colsum_part(const float* __restrict__ hiddens) {
    int c4 = threadIdx.x;                    // 0..255 float4 column
    int r0 = blockIdx.x * (TD / NSPLIT);
    const float4* h4 = (const float4*)hiddens;
    float4 s = make_float4(0.f, 0.f, 0.f, 0.f);
    #pragma unroll 8
    for (int r = 0; r < TD / NSPLIT; ++r) {
        float4 v = h4[(size_t)(r0 + r) * (ED / 4) + c4];
        s.x += v.x; s.y += v.y; s.z += v.z; s.w += v.w;
    }
    ((float4*)g_part[blockIdx.x])[c4] = s;
}

// K1b: reduce NSPLIT partials -> g_att. grid 4, block 64 (1 c4/thread).
__global__ void k_colsum_final() {
    int c4 = blockIdx.x * 64 + threadIdx.x;
    float4 s = make_float4(0.f, 0.f, 0.f, 0.f);
    #pragma unroll 8
    for (int p = 0; p < NSPLIT; ++p) {
        float4 v = ((const float4*)g_part[p])[c4];
        s.x += v.x; s.y += v.y; s.z += v.z; s.w += v.w;
    }
    ((float4*)g_att)[c4] = s;
}

// ============================================================
// K2: LSTM gates. One block (256 thr) per output row r.
// W_i rows (2049 floats) are only 4B-aligned -> scalar loads.
// W_h rows (1024 floats) are 4KB-aligned -> float4 loads.
// ============================================================
__device__ __forceinline__ float sigm(float x) { return 1.f / (1.f + __expf(-x)); }

__global__ void k_gates(
    const float* __restrict__ sen_emb,
    const float* __restrict__ Wii, const float* __restrict__ Wih,
    const float* __restrict__ bii, const float* __restrict__ bih,
    const float* __restrict__ Wfi, const float* __restrict__ Wfh,
    const float* __restrict__ bfi, const float* __restrict__ bfh,
    const float* __restrict__ Wci, const float* __restrict__ Wch,
    const float* __restrict__ bci, const float* __restrict__ bch,
    const float* __restrict__ Woi, const float* __restrict__ Woh,
    const float* __restrict__ boi, const float* __restrict__ boh,
    const float* __restrict__ cur_h, const float* __restrict__ cur_cell,
    const int*   __restrict__ pos_raw)
{
    const int r   = blockIdx.x;
    const int tid = threadIdx.x;
    const size_t oi = (size_t)r * INPD;
    const size_t oh = (size_t)r * HD;

    float ai = 0.f, af = 0.f, ag = 0.f, ao = 0.f;

    // x[0:1024] = sen_emb  (W_i rows unaligned -> scalar)
    for (int k = tid; k < ED; k += 256) {
        float xv = sen_emb[k];
        ai += Wii[oi + k] * xv;
        af += Wfi[oi + k] * xv;
        ag += Wci[oi + k] * xv;
        ao += Woi[oi + k] * xv;
    }
    // x[1024:2048] = att_result
    for (int k = tid; k < ED; k += 256) {
        float xv = g_att[k];
        ai += Wii[oi + 1024 + k] * xv;
        af += Wfi[oi + 1024 + k] * xv;
        ag += Wci[oi + 1024 + k] * xv;
        ao += Woi[oi + 1024 + k] * xv;
    }
    // hidden-state part: W_h rows 4KB-aligned -> float4 (256 thr x 1 float4)
    {
        const float4* wi4 = (const float4*)(Wih + oh);
        const float4* wf4 = (const float4*)(Wfh + oh);
        const float4* wc4 = (const float4*)(Wch + oh);
        const float4* wo4 = (const float4*)(Woh + oh);
        const float4* h4  = (const float4*)cur_h;
        float4 hv = h4[tid];
        float4 w;
        w = wi4[tid]; ai += w.x*hv.x + w.y*hv.y + w.z*hv.z + w.w*hv.w;
        w = wf4[tid]; af += w.x*hv.x + w.y*hv.y + w.z*hv.z + w.w*hv.w;
        w = wc4[tid]; ag += w.x*hv.x + w.y*hv.y + w.z*hv.z + w.w*hv.w;
        w = wo4[tid]; ao += w.x*hv.x + w.y*hv.y + w.z*hv.z + w.w*hv.w;
    }
    // x[2048] = pos_index (robust decode: small int bits vs float bits)
    if (tid == 0) {
        int raw = pos_raw[0];
        float pos = (raw >= -1000000 && raw <= 1000000) ? (float)raw
                                                        : __int_as_float(raw);
        ai += Wii[oi + 2048] * pos;
        af += Wfi[oi + 2048] * pos;
        ag += Wci[oi + 2048] * pos;
        ao += Woi[oi + 2048] * pos;
    }

    #pragma unroll
    for (int o = 16; o; o >>= 1) {
        ai += __shfl_down_sync(0xffffffffu, ai, o);
        af += __shfl_down_sync(0xffffffffu, af, o);
        ag += __shfl_down_sync(0xffffffffu, ag, o);
        ao += __shfl_down_sync(0xffffffffu, ao, o);
    }
    __shared__ float s4[8][4];
    int wid = tid >> 5, lane = tid & 31;
    if (lane == 0) { s4[wid][0] = ai; s4[wid][1] = af; s4[wid][2] = ag; s4[wid][3] = ao; }
    __syncthreads();
    if (tid == 0) {
        float vi = 0.f, vf = 0.f, vg = 0.f, vo = 0.f;
        #pragma unroll
        for (int w = 0; w < 8; ++w) {
            vi += s4[w][0]; vf += s4[w][1]; vg += s4[w][2]; vo += s4[w][3];
        }
        vi += bii[r] + bih[r];
        vf += bfi[r] + bfh[r];
        vg += bci[r] + bch[r];
        vo += boi[r] + boh[r];
        float i = sigm(vi), f = sigm(vf), g = tanhf(vg), o = sigm(vo);
        float c = f * cur_cell[r] + i * g;
        g_h[r] = o * tanhf(c);
    }
}

// ============================================================
// K3a: partial logits. grid (50, JC=32) = 1600 CTAs, block 256.
// 4 consecutive v per thread -> 4 indep accumulator chains.
// dim_out is pure streaming -> __ldcg (L1 bypass).
// ============================================================
__global__ void k_vocab_part(const float* __restrict__ dim_out) {
    __shared__ float hs[JCH];
    const int jc = blockIdx.y;
    const int j0 = jc * JCH;
    if (threadIdx.x < JCH) hs[threadIdx.x] = g_h[j0 + threadIdx.x];
    __syncthreads();

    int v0 = (blockIdx.x * 256 + threadIdx.x) * K3_VPT;
    if (v0 >= VD) return;
    float a0 = 0.f, a1 = 0.f, a2 = 0.f, a3 = 0.f;
    const float* p = dim_out + (size_t)j0 * VD + v0;
    if (v0 + K3_VPT <= VD) {
        #pragma unroll 8
        for (int j = 0; j < JCH; ++j) {
            float hj = hs[j];
            const float* pj = p + (size_t)j * VD;
            a0 += hj * __ldcg(pj + 0);
            a1 += hj * __ldcg(pj + 1);
            a2 += hj * __ldcg(pj + 2);
            a3 += hj * __ldcg(pj + 3);
        }
        g_lpart[jc][v0 + 0] = a0;
        g_lpart[jc][v0 + 1] = a1;
        g_lpart[jc][v0 + 2] = a2;
        g_lpart[jc][v0 + 3] = a3;
    } else {
        for (int v = v0; v < VD; ++v) {
            float acc = 0.f;
            #pragma unroll 8
            for (int j = 0; j < JCH; ++j)
                acc += hs[j] * __ldcg(&dim_out[(size_t)(j0 + j) * VD + v]);
            g_lpart[jc][v] = acc;
        }
    }
}

// ============================================================
// K3b: sum JC partials -> g_logits (float4), AND per-block softmax
// stats (max, sum exp(l - max)). grid NBF=50, block 256, 4 v/thread.
// Pad region [VD,50304) is masked out of the stats.
// ============================================================
__global__ void k_vocab_final() {
    const int tid = threadIdx.x;
    const int v0 = (blockIdx.x * 256 + tid) * 4;

    float l0 = -INFINITY, l1 = -INFINITY, l2 = -INFINITY, l3 = -INFINITY;
    if (v0 + 4 <= VD) {
        float4 s = make_float4(0.f, 0.f, 0.f, 0.f);
        #pragma unroll
        for (int c = 0; c < JC; ++c) {
            float4 p = *(const float4*)&g_lpart[c][v0];
            s.x += p.x; s.y += p.y; s.z += p.z; s.w += p.w;
        }
        *(float4*)&g_logits[v0] = s;
        l0 = s.x; l1 = s.y; l2 = s.z; l3 = s.w;
    } else if (v0 < VD) {
        for (int v = v0; v < VD; ++v) {
            float s = 0.f;
            #pragma unroll
            for (int c = 0; c < JC; ++c) s += g_lpart[c][v];
            g_logits[v] = s;
            if (v == v0)      l0 = s;
            else if (v == v0 + 1) l1 = s;
            else if (v == v0 + 2) l2 = s;
            else              l3 = s;
        }
    }

    // block max
    __shared__ float sw[8];
    float m = fmaxf(fmaxf(l0, l1), fmaxf(l2, l3));
    #pragma unroll
    for (int o = 16; o; o >>= 1) m = fmaxf(m, __shfl_xor_sync(0xffffffffu, m, o));
    if ((tid & 31) == 0) sw[tid >> 5] = m;
    __syncthreads();
    float bm = fmaxf(fmaxf(fmaxf(sw[0], sw[1]), fmaxf(sw[2], sw[3])),
                     fmaxf(fmaxf(sw[4], sw[5]), fmaxf(sw[6], sw[7])));

    // block sum of exp(l - bm), masked
    float e = 0.f;
    if (l0 != -INFINITY) e += expf(l0 - bm);
    if (l1 != -INFINITY) e += expf(l1 - bm);
    if (l2 != -INFINITY) e += expf(l2 - bm);
    if (l3 != -INFINITY) e += expf(l3 - bm);
    #pragma unroll
    for (int o = 16; o; o >>= 1) e += __shfl_xor_sync(0xffffffffu, e, o);
    __syncthreads();              // protect sw reuse
    if ((tid & 31) == 0) sw[tid >> 5] = e;
    __syncthreads();
    if (tid == 0) {
        float s = sw[0] + sw[1] + sw[2] + sw[3] + sw[4] + sw[5] + sw[6] + sw[7];
        g_bmax[blockIdx.x] = bm;
        g_bsum[blockIdx.x] = s;
    }
}

// ============================================================
// K4: normalize. Each block redundantly combines the NBF=50
// per-block stats (L2-resident), then writes its slice of out.
// grid NBF=50, block 256, 4 v/thread.
// ============================================================
__global__ void k_norm(float* __restrict__ out) {
    const int tid = threadIdx.x;   // 256 threads

    // combine stats (every block does this; 50 pairs, L2-hit)
    float m = (tid < NBF) ? g_bmax[tid] : -INFINITY;
    __shared__ float sw[8];
    __shared__ float sM, sInv;
    float t = m;
    #pragma unroll
    for (int o = 16; o; o >>= 1) t = fmaxf(t, __shfl_xor_sync(0xffffffffu, t, o));
    if ((tid & 31) == 0) sw[tid >> 5] = t;
    __syncthreads();
    float M = fmaxf(fmaxf(fmaxf(sw[0], sw[1]), fmaxf(sw[2], sw[3])),
                    fmaxf(fmaxf(sw[4], sw[5]), fmaxf(sw[6], sw[7])));

    float s = (tid < NBF) ? g_bsum[tid] * expf(g_bmax[tid] - M) : 0.f;
    #pragma unroll
    for (int o = 16; o; o >>= 1) s += __shfl_xor_sync(0xffffffffu, s, o);
    __syncthreads();
    if ((tid & 31) == 0) sw[tid >> 5] = s;
    __syncthreads();
    if (tid == 0) {
        float S = sw[0] + sw[1] + sw[2] + sw[3] + sw[4] + sw[5] + sw[6] + sw[7];
        sM = M;
        sInv = 1.f / S;
    }
    __syncthreads();

    float Mv = sM, inv = sInv;
    int v0 = (blockIdx.x * 256 + tid) * 4;
    if (v0 + 4 <= VD) {
        float4 l = *(const float4*)&g_logits[v0];
        float4 r;
        r.x = expf(l.x - Mv) * inv;
        r.y = expf(l.y - Mv) * inv;
        r.z = expf(l.z - Mv) * inv;
        r.w = expf(l.w - Mv) * inv;
        *(float4*)&out[v0] = r;
    } else if (v0 < VD) {
        for (int v = v0; v < VD; ++v)
            out[v] = expf(g_logits[v] - Mv) * inv;
    }
}

// ============================================================
extern "C" void kernel_launch(void* const* d_in, const int* in_sizes, int n_in,
                              void* d_out, int out_size)
{
    const float* sen_emb  = (const float*)d_in[0];
    const float* hiddens  = (const float*)d_in[1];
    const float* dim_out  = (const float*)d_in[2];
    const float* Wii = (const float*)d_in[3];
    const float* Wih = (const float*)d_in[4];
    const float* bii = (const float*)d_in[5];
    const float* bih = (const float*)d_in[6];
    const float* Wfi = (const float*)d_in[7];
    const float* Wfh = (const float*)d_in[8];
    const float* bfi = (const float*)d_in[9];
    const float* bfh = (const float*)d_in[10];
    const float* Wci = (const float*)d_in[11];
    const float* Wch = (const float*)d_in[12];
    const float* bci = (const float*)d_in[13];
    const float* bch = (const float*)d_in[14];
    const float* Woi = (const float*)d_in[15];
    const float* Woh = (const float*)d_in[16];
    const float* boi = (const float*)d_in[17];
    const float* boh = (const float*)d_in[18];
    const float* cur_h    = (const float*)d_in[19];
    const float* cur_cell = (const float*)d_in[20];
    const int*   pos_raw  = (const int*)d_in[21];
    float* out = (float*)d_out;

    // K1: att_result = colsum(hiddens)  (softmax over size-1 axis == all ones)
    k_colsum_part<<<NSPLIT, 256>>>(hiddens);
    k_colsum_final<<<4, 64>>>();

    // K2: LSTM cell -> g_h
    k_gates<<<HD, 256>>>(sen_emb,
                         Wii, Wih, bii, bih,
                         Wfi, Wfh, bfi, bfh,
                         Wci, Wch, bci, bch,
                         Woi, Woh, boi, boh,
                         cur_h, cur_cell, pos_raw);

    // K3: vocab projection, split over v and j (1600 CTAs -> full occupancy)
    int nbv = (VD + 256 * K3_VPT - 1) / (256 * K3_VPT);   // 50
    dim3 g3(nbv, JC);
    k_vocab_part<<<g3, 256>>>(dim_out);
    k_vocab_final<<<NBF, 256>>>();

    // K4: softmax finish (combine folded into norm)
    k_norm<<<NBF, 256>>>(out);
}